// round 2
// baseline (speedup 1.0000x reference)
#include <cuda_runtime.h>
#include <math.h>

#define S_TOTAL 4096
#define EMBED   1280
#define HEADS   16
#define HEAD_DIM 80
#define NSEG    4
#define SEG_LEN 1024

// ---------------- scratch (device globals; no allocation allowed) ----------------
__device__ float g_qkv [S_TOTAL * 3 * EMBED];           // [S][3*E]
__device__ float g_qbuf[HEADS * S_TOTAL * HEAD_DIM];    // [H][S][D]
__device__ float g_kbuf[HEADS * S_TOTAL * HEAD_DIM];
__device__ float g_vbuf[HEADS * S_TOTAL * HEAD_DIM];
__device__ float g_ctx [S_TOTAL * EMBED];               // [S][H*D]

// ---------------- fp32 NT SGEMM: C[m,n] = sum_k A[m,k]*B[n,k] + bias[n] ----------
// BM=BN=128, BK=8, 256 threads, 8x8 accum per thread.
__global__ __launch_bounds__(256) void sgemm_nt(
    const float* __restrict__ A, const float* __restrict__ B,
    const float* __restrict__ bias, float* __restrict__ C,
    int M, int N, int K)
{
    const int BM = 128, BN = 128, BK = 8;
    __shared__ float As[BK][BM];
    __shared__ float Bs[BK][BN];

    int tid = threadIdx.x;
    int bm = blockIdx.y * BM;
    int bn = blockIdx.x * BN;
    int tx = tid & 15;         // 0..15 -> 8 cols each
    int ty = tid >> 4;         // 0..15 -> 8 rows each

    int lRow = tid >> 1;       // 0..127
    int lK   = (tid & 1) * 4;  // 0 or 4

    const float* Aptr = A + (size_t)(bm + lRow) * K + lK;
    const float* Bptr = B + (size_t)(bn + lRow) * K + lK;

    float acc[8][8];
    #pragma unroll
    for (int i = 0; i < 8; i++)
        #pragma unroll
        for (int j = 0; j < 8; j++) acc[i][j] = 0.f;

    for (int k0 = 0; k0 < K; k0 += BK) {
        float4 av = *(const float4*)(Aptr + k0);
        float4 bv = *(const float4*)(Bptr + k0);
        As[lK+0][lRow] = av.x; As[lK+1][lRow] = av.y;
        As[lK+2][lRow] = av.z; As[lK+3][lRow] = av.w;
        Bs[lK+0][lRow] = bv.x; Bs[lK+1][lRow] = bv.y;
        Bs[lK+2][lRow] = bv.z; Bs[lK+3][lRow] = bv.w;
        __syncthreads();

        #pragma unroll
        for (int kk = 0; kk < BK; kk++) {
            float a[8], b[8];
            #pragma unroll
            for (int i = 0; i < 8; i++) a[i] = As[kk][ty*8 + i];
            #pragma unroll
            for (int j = 0; j < 8; j++) b[j] = Bs[kk][tx*8 + j];
            #pragma unroll
            for (int i = 0; i < 8; i++)
                #pragma unroll
                for (int j = 0; j < 8; j++)
                    acc[i][j] += a[i] * b[j];
        }
        __syncthreads();
    }

    #pragma unroll
    for (int i = 0; i < 8; i++) {
        int row = bm + ty*8 + i;
        #pragma unroll
        for (int j = 0; j < 8; j += 4) {
            int col = bn + tx*8 + j;
            float4 o;
            o.x = acc[i][j+0] + bias[col+0];
            o.y = acc[i][j+1] + bias[col+1];
            o.z = acc[i][j+2] + bias[col+2];
            o.w = acc[i][j+3] + bias[col+3];
            *(float4*)(C + (size_t)row * N + col) = o;
        }
    }
}

// ---------------- rotary + transpose scatter -------------------------------------
// qkv[s][t*E + h*80 + d] -> Q/K/V buffers [H][S][D], rotary on Q,K.
__global__ void rotary_scatter(const float* __restrict__ rope)
{
    int idx = blockIdx.x * blockDim.x + threadIdx.x;
    const int TOT = S_TOTAL * HEADS * (HEAD_DIM/2);
    if (idx >= TOT) return;
    int d2 = idx % (HEAD_DIM/2);              // 0..39
    int h  = (idx / (HEAD_DIM/2)) % HEADS;
    int s  = idx / ((HEAD_DIM/2) * HEADS);

    float fr = rope[s*(HEAD_DIM/2) + d2];
    float c  = cosf(fr);
    float sn = sinf(fr);

    const float* qk = g_qkv + (size_t)s * 3 * EMBED;
    int hb = h * HEAD_DIM;
    float q1 = qk[hb + d2],            q2 = qk[hb + d2 + 40];
    float k1 = qk[EMBED + hb + d2],    k2 = qk[EMBED + hb + d2 + 40];
    float v1 = qk[2*EMBED + hb + d2],  v2 = qk[2*EMBED + hb + d2 + 40];

    size_t base = (size_t)h * S_TOTAL * HEAD_DIM + (size_t)s * HEAD_DIM;
    g_qbuf[base + d2]      = q1*c - q2*sn;
    g_qbuf[base + d2 + 40] = q2*c + q1*sn;
    g_kbuf[base + d2]      = k1*c - k2*sn;
    g_kbuf[base + d2 + 40] = k2*c + k1*sn;
    g_vbuf[base + d2]      = v1;
    g_vbuf[base + d2 + 40] = v2;
}

// ---------------- fp32 flash attention (per segment x head) ----------------------
#define BQ   64
#define BKT  64
#define DPAD 81   // odd stride: <=2-way LDS conflicts

__global__ __launch_bounds__(256) void attn_kernel()
{
    extern __shared__ float sm[];
    float* Qs = sm;                       // BQ  x DPAD
    float* Ks = Qs + BQ * DPAD;           // BKT x DPAD
    float* Vs = Ks + BKT * DPAD;          // BKT x DPAD
    float* Ps = Vs + BKT * DPAD;          // BQ  x BKT

    int tid = threadIdx.x;
    int qt  = blockIdx.x;   // 0..15
    int h   = blockIdx.y;   // 0..15
    int seg = blockIdx.z;   // 0..3
    int tr  = tid >> 4;     // 0..15 -> 4 q rows each
    int tc  = tid & 15;     // 0..15 -> 4 s cols / 5 d cols each

    const float scale = 1.0f / sqrtf((float)HEAD_DIM);
    size_t hbase = (size_t)h * S_TOTAL * HEAD_DIM;
    const float* Qg = g_qbuf + hbase + (size_t)(seg*SEG_LEN + qt*BQ) * HEAD_DIM;
    const float* Kg = g_kbuf + hbase + (size_t)seg * SEG_LEN * HEAD_DIM;
    const float* Vg = g_vbuf + hbase + (size_t)seg * SEG_LEN * HEAD_DIM;

    // load Q tile (pre-scaled)
    for (int i = tid; i < BQ*HEAD_DIM; i += 256) {
        int r = i / HEAD_DIM, c = i % HEAD_DIM;
        Qs[r*DPAD + c] = Qg[i] * scale;
    }

    float m[4], l[4], o[4][5];
    #pragma unroll
    for (int i = 0; i < 4; i++) {
        m[i] = -INFINITY; l[i] = 0.f;
        #pragma unroll
        for (int dd = 0; dd < 5; dd++) o[i][dd] = 0.f;
    }

    for (int kt = 0; kt < SEG_LEN / BKT; kt++) {
        __syncthreads();   // protect Ks/Vs/Ps from prior iteration readers
        for (int i = tid; i < BKT*HEAD_DIM; i += 256) {
            int r = i / HEAD_DIM, c = i % HEAD_DIM;
            Ks[r*DPAD + c] = Kg[(size_t)kt*BKT*HEAD_DIM + i];
            Vs[r*DPAD + c] = Vg[(size_t)kt*BKT*HEAD_DIM + i];
        }
        __syncthreads();

        // S = Q K^T (4x4 micro-tile per thread)
        float s[4][4];
        #pragma unroll
        for (int i = 0; i < 4; i++)
            #pragma unroll
            for (int j = 0; j < 4; j++) s[i][j] = 0.f;

        #pragma unroll 8
        for (int d = 0; d < HEAD_DIM; d++) {
            float a[4], b[4];
            #pragma unroll
            for (int i = 0; i < 4; i++) a[i] = Qs[(4*tr+i)*DPAD + d];
            #pragma unroll
            for (int j = 0; j < 4; j++) b[j] = Ks[(4*tc+j)*DPAD + d];
            #pragma unroll
            for (int i = 0; i < 4; i++)
                #pragma unroll
                for (int j = 0; j < 4; j++)
                    s[i][j] += a[i] * b[j];
        }

        // online softmax (row groups share 16 consecutive lanes -> shuffle reduce)
        #pragma unroll
        for (int i = 0; i < 4; i++) {
            float mt = s[i][0];
            #pragma unroll
            for (int j = 1; j < 4; j++) mt = fmaxf(mt, s[i][j]);
            #pragma unroll
            for (int off = 8; off >= 1; off >>= 1)
                mt = fmaxf(mt, __shfl_xor_sync(0xffffffffu, mt, off));
            float mn = fmaxf(m[i], mt);
            float alpha = __expf(m[i] - mn);
            float rs = 0.f;
            #pragma unroll
            for (int j = 0; j < 4; j++) {
                float p = __expf(s[i][j] - mn);
                s[i][j] = p;
                rs += p;
            }
            #pragma unroll
            for (int off = 8; off >= 1; off >>= 1)
                rs += __shfl_xor_sync(0xffffffffu, rs, off);
            l[i] = l[i] * alpha + rs;
            m[i] = mn;
            #pragma unroll
            for (int dd = 0; dd < 5; dd++) o[i][dd] *= alpha;
            #pragma unroll
            for (int j = 0; j < 4; j++)
                Ps[(4*tr+i)*BKT + 4*tc + j] = s[i][j];
        }
        __syncthreads();

        // O += P V  (thread owns 4 rows x 5 d-cols)
        #pragma unroll 4
        for (int j = 0; j < BKT; j++) {
            float v[5];
            #pragma unroll
            for (int dd = 0; dd < 5; dd++) v[dd] = Vs[j*DPAD + tc*5 + dd];
            #pragma unroll
            for (int i = 0; i < 4; i++) {
                float p = Ps[(4*tr+i)*BKT + j];
                #pragma unroll
                for (int dd = 0; dd < 5; dd++) o[i][dd] += p * v[dd];
            }
        }
    }

    // write ctx[s][h*80 + d]
    #pragma unroll
    for (int i = 0; i < 4; i++) {
        int srow = seg*SEG_LEN + qt*BQ + 4*tr + i;
        float inv = 1.0f / l[i];
        #pragma unroll
        for (int dd = 0; dd < 5; dd++)
            g_ctx[(size_t)srow * EMBED + h*HEAD_DIM + tc*5 + dd] = o[i][dd] * inv;
    }
}

// ---------------- launch ----------------------------------------------------------
extern "C" void kernel_launch(void* const* d_in, const int* in_sizes, int n_in,
                              void* d_out, int out_size)
{
    const float* x      = (const float*)d_in[0];
    const float* qkv_w  = (const float*)d_in[1];
    const float* qkv_b  = (const float*)d_in[2];
    const float* proj_w = (const float*)d_in[3];
    const float* proj_b = (const float*)d_in[4];
    const float* rope   = (const float*)d_in[5];
    float* out = (float*)d_out;

    float *qkv_p, *ctx_p;
    cudaGetSymbolAddress((void**)&qkv_p, g_qkv);
    cudaGetSymbolAddress((void**)&ctx_p, g_ctx);

    // 1) QKV GEMM: [4096,3840] = x[4096,1280] * qkv_w[3840,1280]^T + b
    dim3 g1(3 * EMBED / 128, S_TOTAL / 128);
    sgemm_nt<<<g1, 256>>>(x, qkv_w, qkv_b, qkv_p, S_TOTAL, 3 * EMBED, EMBED);

    // 2) rotary + transpose into [H][S][D]
    int nrot = S_TOTAL * HEADS * (HEAD_DIM / 2);
    rotary_scatter<<<(nrot + 255) / 256, 256>>>(rope);

    // 3) attention
    int smem = (BQ * DPAD + 2 * BKT * DPAD + BQ * BKT) * (int)sizeof(float);
    cudaFuncSetAttribute(attn_kernel, cudaFuncAttributeMaxDynamicSharedMemorySize, smem);
    attn_kernel<<<dim3(16, HEADS, NSEG), 256, smem>>>();

    // 4) proj GEMM: out[4096,1280] = ctx[4096,1280] * proj_w[1280,1280]^T + b
    dim3 g2(EMBED / 128, S_TOTAL / 128);
    sgemm_nt<<<g2, 256>>>(ctx_p, proj_w, proj_b, out, S_TOTAL, EMBED, EMBED);
}

// round 4
// speedup vs baseline: 1.6438x; 1.6438x over previous
#include <cuda_runtime.h>
#include <cuda_bf16.h>
#include <math.h>
#include <stdint.h>

#define S_TOTAL 4096
#define EMBED   1280
#define HEADS   16
#define HEAD_DIM 80
#define NSEG    4
#define SEG_LEN 1024

#define KP2     2560          // [hi|lo] bf16 storage cols per row
#define NCH     120           // K' = 3*1280 = 3840 -> 120 chunks of 32
#define BM      128
#define BN      128
#define BKC     32            // bf16 k per chunk
#define KPAD    40            // padded smem row stride (bf16 elems) -> 80B

// ---------------- scratch ----------------
__device__ float g_qkv [S_TOTAL * 3 * EMBED];           // [S][3E]
__device__ float g_qbuf[HEADS * S_TOTAL * HEAD_DIM];    // [H][S][D]
__device__ float g_kbuf[HEADS * S_TOTAL * HEAD_DIM];
__device__ float g_vbuf[HEADS * S_TOTAL * HEAD_DIM];
__device__ float g_ctx [S_TOTAL * EMBED];               // [S][H*D]
__device__ __nv_bfloat16 g_A2   [S_TOTAL * KP2];        // split act  [hi|lo]
__device__ __nv_bfloat16 g_Bqkv [3 * EMBED * KP2];      // split qkv_w
__device__ __nv_bfloat16 g_Bproj[EMBED * KP2];          // split proj_w

// ---------------- helpers ----------------
__device__ __forceinline__ uint32_t s2u(const void* p) {
    uint32_t a;
    asm("{ .reg .u64 t; cvta.to.shared.u64 t, %1; cvt.u32.u64 %0, t; }" : "=r"(a) : "l"(p));
    return a;
}
__device__ __forceinline__ void cpa16(uint32_t dst, const void* src) {
    asm volatile("cp.async.cg.shared.global [%0], [%1], 16;" :: "r"(dst), "l"(src) : "memory");
}
#define CP_COMMIT() asm volatile("cp.async.commit_group;" ::: "memory")
#define CP_WAIT(n)  asm volatile("cp.async.wait_group %0;" :: "n"(n) : "memory")

// ---------------- fp32 -> bf16 [hi|lo] split ----------------
__global__ void split_bf16(const float* __restrict__ src, __nv_bfloat16* __restrict__ dst, int total)
{
    int i = blockIdx.x * 256 + threadIdx.x;
    if (i >= total) return;
    int r = i / EMBED, c = i % EMBED;
    float a = src[i];
    __nv_bfloat16 h = __float2bfloat16(a);
    float res = a - __bfloat162float(h);
    dst[(size_t)r * KP2 + c]         = h;
    dst[(size_t)r * KP2 + EMBED + c] = __float2bfloat16(res);
}

// ---------------- HMMA split-bf16 GEMM: C[M,N] = A·B^T + bias -------------------
// A,B in split layout [rows][hi(1280)|lo(1280)] bf16. Virtual K'=3840:
// chunks 0-39: Ah·Bh, 40-79: Ah·Bl, 80-119: Al·Bh.
__global__ __launch_bounds__(256, 2) void hmma_gemm(
    const __nv_bfloat16* __restrict__ A,
    const __nv_bfloat16* __restrict__ B,
    const float* __restrict__ bias,
    float* __restrict__ C, int Ntot)
{
    __shared__ __nv_bfloat16 Asm[2][BM * KPAD];
    __shared__ __nv_bfloat16 Bsm[2][BN * KPAD];

    int tid = threadIdx.x, wid = tid >> 5, lane = tid & 31;
    int bm = blockIdx.y * BM, bn = blockIdx.x * BN;
    int wm = (wid >> 2) * 64;    // warp row base (0 or 64)
    int wn = (wid & 3) * 32;     // warp col base

    float acc[4][4][4];
    #pragma unroll
    for (int i = 0; i < 4; i++)
        #pragma unroll
        for (int j = 0; j < 4; j++)
            #pragma unroll
            for (int v = 0; v < 4; v++) acc[i][j][v] = 0.f;

    uint32_t aS[2] = { s2u(Asm[0]), s2u(Asm[1]) };
    uint32_t bS[2] = { s2u(Bsm[0]), s2u(Bsm[1]) };

    // loader: 128 rows x 64B per tile = 512 x 16B; each thread: 2 A + 2 B
    #define LOADC(cc, buf) do { \
        int _c = (cc); \
        int _ak = (_c < 40) ? _c * 32 : ((_c < 80) ? (_c - 40) * 32 : EMBED + (_c - 80) * 32); \
        int _bk = (_c < 40) ? _c * 32 : ((_c < 80) ? EMBED + (_c - 40) * 32 : (_c - 80) * 32); \
        const __nv_bfloat16* _Ag = A + (size_t)bm * KP2 + _ak; \
        const __nv_bfloat16* _Bg = B + (size_t)bn * KP2 + _bk; \
        _Pragma("unroll") \
        for (int _t = 0; _t < 2; _t++) { \
            int _id = tid + _t * 256; \
            int _r = _id >> 2, _o = (_id & 3) * 8; \
            cpa16(aS[buf] + (_r * KPAD + _o) * 2, _Ag + (size_t)_r * KP2 + _o); \
            cpa16(bS[buf] + (_r * KPAD + _o) * 2, _Bg + (size_t)_r * KP2 + _o); \
        } \
    } while (0)

    LOADC(0, 0);
    CP_COMMIT();

    for (int i = 0; i < NCH; i++) {
        int buf = i & 1;
        if (i + 1 < NCH) {
            LOADC(i + 1, (i + 1) & 1);
            CP_COMMIT();
            CP_WAIT(1);
        } else {
            CP_WAIT(0);
        }
        __syncthreads();

        uint32_t ab = aS[buf], bb = bS[buf];
        #pragma unroll
        for (int ks = 0; ks < 2; ks++) {
            int k0 = ks * 16;
            uint32_t bf[4][2];
            #pragma unroll
            for (int nt = 0; nt < 4; nt++) {
                int row = wn + nt * 8 + (lane & 7);
                int ko = k0 + ((lane >> 3) & 1) * 8;
                uint32_t addr = bb + (row * KPAD + ko) * 2;
                asm volatile("ldmatrix.sync.aligned.m8n8.x2.shared.b16 {%0,%1}, [%2];"
                    : "=r"(bf[nt][0]), "=r"(bf[nt][1]) : "r"(addr));
            }
            #pragma unroll
            for (int mt = 0; mt < 4; mt++) {
                int row = wm + mt * 16 + (lane & 15);
                int ko = k0 + (lane >> 4) * 8;
                uint32_t addr = ab + (row * KPAD + ko) * 2;
                uint32_t a0, a1, a2, a3;
                asm volatile("ldmatrix.sync.aligned.m8n8.x4.shared.b16 {%0,%1,%2,%3}, [%4];"
                    : "=r"(a0), "=r"(a1), "=r"(a2), "=r"(a3) : "r"(addr));
                #pragma unroll
                for (int nt = 0; nt < 4; nt++) {
                    asm volatile(
                        "mma.sync.aligned.m16n8k16.row.col.f32.bf16.bf16.f32 "
                        "{%0,%1,%2,%3}, {%4,%5,%6,%7}, {%8,%9}, {%0,%1,%2,%3};"
                        : "+f"(acc[mt][nt][0]), "+f"(acc[mt][nt][1]),
                          "+f"(acc[mt][nt][2]), "+f"(acc[mt][nt][3])
                        : "r"(a0), "r"(a1), "r"(a2), "r"(a3),
                          "r"(bf[nt][0]), "r"(bf[nt][1]));
                }
            }
        }
        __syncthreads();
    }
    #undef LOADC

    // epilogue: c0,c1 -> row g, cols t*2,t*2+1 ; c2,c3 -> row g+8
    int g = lane >> 2, t = lane & 3;
    #pragma unroll
    for (int mt = 0; mt < 4; mt++) {
        #pragma unroll
        for (int nt = 0; nt < 4; nt++) {
            int row = bm + wm + mt * 16 + g;
            int col = bn + wn + nt * 8 + t * 2;
            float b0 = bias[col], b1 = bias[col + 1];
            float2* p0 = (float2*)(C + (size_t)row * Ntot + col);
            float2* p1 = (float2*)(C + (size_t)(row + 8) * Ntot + col);
            *p0 = make_float2(acc[mt][nt][0] + b0, acc[mt][nt][1] + b1);
            *p1 = make_float2(acc[mt][nt][2] + b0, acc[mt][nt][3] + b1);
        }
    }
}

// ---------------- rotary + transpose scatter ----------------
__global__ void rotary_scatter(const float* __restrict__ rope)
{
    int idx = blockIdx.x * blockDim.x + threadIdx.x;
    const int TOT = S_TOTAL * HEADS * (HEAD_DIM / 2);
    if (idx >= TOT) return;
    int d2 = idx % (HEAD_DIM / 2);
    int h  = (idx / (HEAD_DIM / 2)) % HEADS;
    int s  = idx / ((HEAD_DIM / 2) * HEADS);

    float fr = rope[s * (HEAD_DIM / 2) + d2];
    float c = cosf(fr), sn = sinf(fr);

    const float* qk = g_qkv + (size_t)s * 3 * EMBED;
    int hb = h * HEAD_DIM;
    float q1 = qk[hb + d2],              q2 = qk[hb + d2 + 40];
    float k1 = qk[EMBED + hb + d2],      k2 = qk[EMBED + hb + d2 + 40];
    float v1 = qk[2 * EMBED + hb + d2],  v2 = qk[2 * EMBED + hb + d2 + 40];

    size_t base = (size_t)h * S_TOTAL * HEAD_DIM + (size_t)s * HEAD_DIM;
    g_qbuf[base + d2]      = q1 * c - q2 * sn;
    g_qbuf[base + d2 + 40] = q2 * c + q1 * sn;
    g_kbuf[base + d2]      = k1 * c - k2 * sn;
    g_kbuf[base + d2 + 40] = k2 * c + k1 * sn;
    g_vbuf[base + d2]      = v1;
    g_vbuf[base + d2 + 40] = v2;
}

// ---------------- fp32 flash attention ----------------
#define BQ   64
#define BKT  64
#define DPAD 81

__global__ __launch_bounds__(256) void attn_kernel()
{
    extern __shared__ float smf[];
    float* Qs = smf;
    float* Ks = Qs + BQ * DPAD;
    float* Vs = Ks + BKT * DPAD;
    float* Ps = Vs + BKT * DPAD;

    int tid = threadIdx.x;
    int qt  = blockIdx.x;
    int h   = blockIdx.y;
    int seg = blockIdx.z;
    int tr  = tid >> 4;
    int tc  = tid & 15;

    const float scale = 1.0f / sqrtf((float)HEAD_DIM);
    size_t hbase = (size_t)h * S_TOTAL * HEAD_DIM;
    const float* Qg = g_qbuf + hbase + (size_t)(seg * SEG_LEN + qt * BQ) * HEAD_DIM;
    const float* Kg = g_kbuf + hbase + (size_t)seg * SEG_LEN * HEAD_DIM;
    const float* Vg = g_vbuf + hbase + (size_t)seg * SEG_LEN * HEAD_DIM;

    for (int i = tid; i < BQ * HEAD_DIM; i += 256) {
        int r = i / HEAD_DIM, c = i % HEAD_DIM;
        Qs[r * DPAD + c] = Qg[i] * scale;
    }

    float m[4], l[4], o[4][5];
    #pragma unroll
    for (int i = 0; i < 4; i++) {
        m[i] = -INFINITY; l[i] = 0.f;
        #pragma unroll
        for (int dd = 0; dd < 5; dd++) o[i][dd] = 0.f;
    }

    for (int kt = 0; kt < SEG_LEN / BKT; kt++) {
        __syncthreads();
        for (int i = tid; i < BKT * HEAD_DIM; i += 256) {
            int r = i / HEAD_DIM, c = i % HEAD_DIM;
            Ks[r * DPAD + c] = Kg[(size_t)kt * BKT * HEAD_DIM + i];
            Vs[r * DPAD + c] = Vg[(size_t)kt * BKT * HEAD_DIM + i];
        }
        __syncthreads();

        float s[4][4];
        #pragma unroll
        for (int i = 0; i < 4; i++)
            #pragma unroll
            for (int j = 0; j < 4; j++) s[i][j] = 0.f;

        #pragma unroll 8
        for (int d = 0; d < HEAD_DIM; d++) {
            float a[4], b[4];
            #pragma unroll
            for (int i = 0; i < 4; i++) a[i] = Qs[(4 * tr + i) * DPAD + d];
            #pragma unroll
            for (int j = 0; j < 4; j++) b[j] = Ks[(4 * tc + j) * DPAD + d];
            #pragma unroll
            for (int i = 0; i < 4; i++)
                #pragma unroll
                for (int j = 0; j < 4; j++)
                    s[i][j] += a[i] * b[j];
        }

        #pragma unroll
        for (int i = 0; i < 4; i++) {
            float mt = s[i][0];
            #pragma unroll
            for (int j = 1; j < 4; j++) mt = fmaxf(mt, s[i][j]);
            #pragma unroll
            for (int off = 8; off >= 1; off >>= 1)
                mt = fmaxf(mt, __shfl_xor_sync(0xffffffffu, mt, off));
            float mn = fmaxf(m[i], mt);
            float alpha = __expf(m[i] - mn);
            float rs = 0.f;
            #pragma unroll
            for (int j = 0; j < 4; j++) {
                float p = __expf(s[i][j] - mn);
                s[i][j] = p;
                rs += p;
            }
            #pragma unroll
            for (int off = 8; off >= 1; off >>= 1)
                rs += __shfl_xor_sync(0xffffffffu, rs, off);
            l[i] = l[i] * alpha + rs;
            m[i] = mn;
            #pragma unroll
            for (int dd = 0; dd < 5; dd++) o[i][dd] *= alpha;
            #pragma unroll
            for (int j = 0; j < 4; j++)
                Ps[(4 * tr + i) * BKT + 4 * tc + j] = s[i][j];
        }
        __syncthreads();

        #pragma unroll 4
        for (int j = 0; j < BKT; j++) {
            float v[5];
            #pragma unroll
            for (int dd = 0; dd < 5; dd++) v[dd] = Vs[j * DPAD + tc * 5 + dd];
            #pragma unroll
            for (int i = 0; i < 4; i++) {
                float p = Ps[(4 * tr + i) * BKT + j];
                #pragma unroll
                for (int dd = 0; dd < 5; dd++) o[i][dd] += p * v[dd];
            }
        }
    }

    #pragma unroll
    for (int i = 0; i < 4; i++) {
        int srow = seg * SEG_LEN + qt * BQ + 4 * tr + i;
        float inv = 1.0f / l[i];
        #pragma unroll
        for (int dd = 0; dd < 5; dd++)
            g_ctx[(size_t)srow * EMBED + h * HEAD_DIM + tc * 5 + dd] = o[i][dd] * inv;
    }
}

// ---------------- launch ----------------
extern "C" void kernel_launch(void* const* d_in, const int* in_sizes, int n_in,
                              void* d_out, int out_size)
{
    const float* x      = (const float*)d_in[0];
    const float* qkv_w  = (const float*)d_in[1];
    const float* qkv_b  = (const float*)d_in[2];
    const float* proj_w = (const float*)d_in[3];
    const float* proj_b = (const float*)d_in[4];
    const float* rope   = (const float*)d_in[5];
    float* out = (float*)d_out;

    float *qkv_p, *ctx_p;
    __nv_bfloat16 *a2_p, *bqkv_p, *bproj_p;
    cudaGetSymbolAddress((void**)&qkv_p,   g_qkv);
    cudaGetSymbolAddress((void**)&ctx_p,   g_ctx);
    cudaGetSymbolAddress((void**)&a2_p,    g_A2);
    cudaGetSymbolAddress((void**)&bqkv_p,  g_Bqkv);
    cudaGetSymbolAddress((void**)&bproj_p, g_Bproj);

    int nx = S_TOTAL * EMBED;
    int nw = 3 * EMBED * EMBED;
    int np = EMBED * EMBED;
    split_bf16<<<(nx + 255) / 256, 256>>>(x, a2_p, nx);
    split_bf16<<<(nw + 255) / 256, 256>>>(qkv_w, bqkv_p, nw);
    split_bf16<<<(np + 255) / 256, 256>>>(proj_w, bproj_p, np);

    // 1) QKV GEMM (HMMA): [4096, 3840]
    hmma_gemm<<<dim3(3 * EMBED / BN, S_TOTAL / BM), 256>>>(
        a2_p, bqkv_p, qkv_b, qkv_p, 3 * EMBED);

    // 2) rotary + transpose
    int nrot = S_TOTAL * HEADS * (HEAD_DIM / 2);
    rotary_scatter<<<(nrot + 255) / 256, 256>>>(rope);

    // 3) attention
    int asmem = (BQ * DPAD + 2 * BKT * DPAD + BQ * BKT) * (int)sizeof(float);
    cudaFuncSetAttribute(attn_kernel, cudaFuncAttributeMaxDynamicSharedMemorySize, asmem);
    attn_kernel<<<dim3(16, HEADS, NSEG), 256, asmem>>>();

    // 4) ctx split + proj GEMM (HMMA): [4096, 1280]
    split_bf16<<<(nx + 255) / 256, 256>>>(ctx_p, a2_p, nx);
    hmma_gemm<<<dim3(EMBED / BN, S_TOTAL / BM), 256>>>(
        a2_p, bproj_p, proj_b, out, EMBED);
}

// round 5
// speedup vs baseline: 2.2671x; 1.3792x over previous
#include <cuda_runtime.h>
#include <cuda_bf16.h>
#include <math.h>
#include <stdint.h>

#define S_TOTAL 4096
#define EMBED   1280
#define HEADS   16
#define HEAD_DIM 80
#define NSEG    4
#define SEG_LEN 1024

#define KP2     2560          // [hi|lo] bf16 storage cols per row
#define NCH     120           // K' = 3*1280 -> 120 chunks of 32
#define BM      128
#define BN      128
#define KPAD    40            // gemm smem row stride (bf16)

// attention tiles
#define AQ      128
#define AK      64
#define QSTR    88            // q/k smem row stride (odd*8 -> conflict-free ldmatrix)
#define VSTR    72            // v^T smem row stride

// ---------------- scratch ----------------
__device__ float g_qkv [S_TOTAL * 3 * EMBED];                 // [S][3E] fp32
__device__ __nv_bfloat16 g_A2   [S_TOTAL * KP2];              // split activations [hi|lo]
__device__ __nv_bfloat16 g_Bqkv [3 * EMBED * KP2];
__device__ __nv_bfloat16 g_Bproj[EMBED * KP2];
__device__ __nv_bfloat16 g_Qh[HEADS * S_TOTAL * HEAD_DIM];    // [H][S][D] (scaled)
__device__ __nv_bfloat16 g_Ql[HEADS * S_TOTAL * HEAD_DIM];
__device__ __nv_bfloat16 g_Kh[HEADS * S_TOTAL * HEAD_DIM];
__device__ __nv_bfloat16 g_Kl[HEADS * S_TOTAL * HEAD_DIM];
__device__ __nv_bfloat16 g_Vth[HEADS * HEAD_DIM * S_TOTAL];   // [H][D][S]
__device__ __nv_bfloat16 g_Vtl[HEADS * HEAD_DIM * S_TOTAL];

// ---------------- helpers ----------------
__device__ __forceinline__ uint32_t s2u(const void* p) {
    uint32_t a;
    asm("{ .reg .u64 t; cvta.to.shared.u64 t, %1; cvt.u32.u64 %0, t; }" : "=r"(a) : "l"(p));
    return a;
}
__device__ __forceinline__ void cpa16(uint32_t dst, const void* src) {
    asm volatile("cp.async.cg.shared.global [%0], [%1], 16;" :: "r"(dst), "l"(src) : "memory");
}
#define CP_COMMIT() asm volatile("cp.async.commit_group;" ::: "memory")
#define CP_WAIT(n)  asm volatile("cp.async.wait_group %0;" :: "n"(n) : "memory")

__device__ __forceinline__ void ldmx4(uint32_t addr, uint32_t* r) {
    asm volatile("ldmatrix.sync.aligned.m8n8.x4.shared.b16 {%0,%1,%2,%3}, [%4];"
        : "=r"(r[0]), "=r"(r[1]), "=r"(r[2]), "=r"(r[3]) : "r"(addr));
}
__device__ __forceinline__ void ldmx2(uint32_t addr, uint32_t* r) {
    asm volatile("ldmatrix.sync.aligned.m8n8.x2.shared.b16 {%0,%1}, [%2];"
        : "=r"(r[0]), "=r"(r[1]) : "r"(addr));
}
__device__ __forceinline__ void mma16816(float* c, const uint32_t* a, const uint32_t* b) {
    asm volatile(
        "mma.sync.aligned.m16n8k16.row.col.f32.bf16.bf16.f32 "
        "{%0,%1,%2,%3},{%4,%5,%6,%7},{%8,%9},{%0,%1,%2,%3};"
        : "+f"(c[0]), "+f"(c[1]), "+f"(c[2]), "+f"(c[3])
        : "r"(a[0]), "r"(a[1]), "r"(a[2]), "r"(a[3]), "r"(b[0]), "r"(b[1]));
}
// e^x on the FMA pipe (exp2 poly, err ~2e-8)
__device__ __forceinline__ float fexp(float x) {
    float t = x * 1.4426950408889634f;
    t = fmaxf(t, -126.0f);
    float fi = floorf(t);
    float f = t - fi;
    float p = 1.33336498e-3f;
    p = fmaf(p, f, 9.61011733e-3f);
    p = fmaf(p, f, 5.55036243e-2f);
    p = fmaf(p, f, 2.40226506e-1f);
    p = fmaf(p, f, 6.93147182e-1f);
    p = fmaf(p, f, 1.0f);
    return p * __int_as_float(((int)fi + 127) << 23);
}
__device__ __forceinline__ void split2(float v, __nv_bfloat16& h, __nv_bfloat16& l) {
    h = __float2bfloat16(v);
    l = __float2bfloat16(v - __bfloat162float(h));
}
__device__ __forceinline__ uint32_t packbf(__nv_bfloat16 a, __nv_bfloat16 b) {
    return (uint32_t)__bfloat16_as_ushort(a) | ((uint32_t)__bfloat16_as_ushort(b) << 16);
}

// ---------------- fp32 -> bf16 [hi|lo] split ----------------
__global__ void split_bf16(const float* __restrict__ src, __nv_bfloat16* __restrict__ dst, int total)
{
    int i = blockIdx.x * 256 + threadIdx.x;
    if (i >= total) return;
    int r = i / EMBED, c = i % EMBED;
    float a = src[i];
    __nv_bfloat16 h = __float2bfloat16(a);
    float res = a - __bfloat162float(h);
    dst[(size_t)r * KP2 + c]         = h;
    dst[(size_t)r * KP2 + EMBED + c] = __float2bfloat16(res);
}

// ---------------- HMMA split-bf16 GEMM (3-stage pipeline) -----------------------
__global__ __launch_bounds__(256, 2) void hmma_gemm(
    const __nv_bfloat16* __restrict__ A,
    const __nv_bfloat16* __restrict__ B,
    const float* __restrict__ bias,
    float* __restrict__ C, int Ntot)
{
    extern __shared__ char smraw[];
    uint32_t aS[3], bS[3];
    {
        uint32_t base = s2u(smraw);
        #pragma unroll
        for (int s = 0; s < 3; s++) { aS[s] = base + s * 20480; bS[s] = base + s * 20480 + 10240; }
    }

    int tid = threadIdx.x, wid = tid >> 5, lane = tid & 31;
    int bm = blockIdx.y * BM, bn = blockIdx.x * BN;
    int wm = (wid >> 2) * 64;
    int wn = (wid & 3) * 32;

    float acc[4][4][4];
    #pragma unroll
    for (int i = 0; i < 4; i++)
        #pragma unroll
        for (int j = 0; j < 4; j++)
            #pragma unroll
            for (int v = 0; v < 4; v++) acc[i][j][v] = 0.f;

    #define LOADC(cc, buf) do { \
        int _c = (cc); \
        int _ak = (_c < 40) ? _c * 32 : ((_c < 80) ? (_c - 40) * 32 : EMBED + (_c - 80) * 32); \
        int _bk = (_c < 40) ? _c * 32 : ((_c < 80) ? EMBED + (_c - 40) * 32 : (_c - 80) * 32); \
        const __nv_bfloat16* _Ag = A + (size_t)bm * KP2 + _ak; \
        const __nv_bfloat16* _Bg = B + (size_t)bn * KP2 + _bk; \
        _Pragma("unroll") \
        for (int _t = 0; _t < 2; _t++) { \
            int _id = tid + _t * 256; \
            int _r = _id >> 2, _o = (_id & 3) * 8; \
            cpa16(aS[buf] + (_r * KPAD + _o) * 2, _Ag + (size_t)_r * KP2 + _o); \
            cpa16(bS[buf] + (_r * KPAD + _o) * 2, _Bg + (size_t)_r * KP2 + _o); \
        } \
    } while (0)

    LOADC(0, 0); CP_COMMIT();
    LOADC(1, 1); CP_COMMIT();

    for (int i = 0; i < NCH; i++) {
        if (i + 2 < NCH) LOADC(i + 2, (i + 2) % 3);
        CP_COMMIT();
        CP_WAIT(2);
        __syncthreads();

        uint32_t ab = aS[i % 3], bb = bS[i % 3];
        #pragma unroll
        for (int ks = 0; ks < 2; ks++) {
            int k0 = ks * 16;
            uint32_t bf[4][2];
            #pragma unroll
            for (int nt = 0; nt < 4; nt++) {
                int row = wn + nt * 8 + (lane & 7);
                int ko = k0 + ((lane >> 3) & 1) * 8;
                ldmx2(bb + (row * KPAD + ko) * 2, bf[nt]);
            }
            #pragma unroll
            for (int mt = 0; mt < 4; mt++) {
                int row = wm + mt * 16 + (lane & 15);
                int ko = k0 + (lane >> 4) * 8;
                uint32_t af[4];
                ldmx4(ab + (row * KPAD + ko) * 2, af);
                #pragma unroll
                for (int nt = 0; nt < 4; nt++)
                    mma16816(acc[mt][nt], af, bf[nt]);
            }
        }
        __syncthreads();
    }
    #undef LOADC

    int g = lane >> 2, t = lane & 3;
    #pragma unroll
    for (int mt = 0; mt < 4; mt++) {
        #pragma unroll
        for (int nt = 0; nt < 4; nt++) {
            int row = bm + wm + mt * 16 + g;
            int col = bn + wn + nt * 8 + t * 2;
            float b0 = bias[col], b1 = bias[col + 1];
            float2* p0 = (float2*)(C + (size_t)row * Ntot + col);
            float2* p1 = (float2*)(C + (size_t)(row + 8) * Ntot + col);
            *p0 = make_float2(acc[mt][nt][0] + b0, acc[mt][nt][1] + b1);
            *p1 = make_float2(acc[mt][nt][2] + b0, acc[mt][nt][3] + b1);
        }
    }
}

// ---------------- rotary + split + transpose scatter ----------------
__global__ void rotary_split(const float* __restrict__ rope)
{
    int idx = blockIdx.x * blockDim.x + threadIdx.x;
    const int TOT = S_TOTAL * HEADS * (HEAD_DIM / 2);
    if (idx >= TOT) return;
    int d2 = idx % (HEAD_DIM / 2);
    int h  = (idx / (HEAD_DIM / 2)) % HEADS;
    int s  = idx / ((HEAD_DIM / 2) * HEADS);

    float fr = rope[s * (HEAD_DIM / 2) + d2];
    float c = cosf(fr), sn = sinf(fr);
    const float scale = 0.111803398875f;  // 1/sqrt(80)

    const float* qk = g_qkv + (size_t)s * 3 * EMBED;
    int hb = h * HEAD_DIM;
    float q1 = qk[hb + d2],              q2 = qk[hb + d2 + 40];
    float k1 = qk[EMBED + hb + d2],      k2 = qk[EMBED + hb + d2 + 40];
    float v1 = qk[2 * EMBED + hb + d2],  v2 = qk[2 * EMBED + hb + d2 + 40];

    float qa = (q1 * c - q2 * sn) * scale;
    float qb = (q2 * c + q1 * sn) * scale;
    float ka = k1 * c - k2 * sn;
    float kb = k2 * c + k1 * sn;

    size_t base = (size_t)h * S_TOTAL * HEAD_DIM + (size_t)s * HEAD_DIM;
    __nv_bfloat16 hh, ll;
    split2(qa, hh, ll); g_Qh[base + d2] = hh;      g_Ql[base + d2] = ll;
    split2(qb, hh, ll); g_Qh[base + d2 + 40] = hh; g_Ql[base + d2 + 40] = ll;
    split2(ka, hh, ll); g_Kh[base + d2] = hh;      g_Kl[base + d2] = ll;
    split2(kb, hh, ll); g_Kh[base + d2 + 40] = hh; g_Kl[base + d2 + 40] = ll;

    size_t vb0 = (size_t)h * HEAD_DIM * S_TOTAL + (size_t)d2 * S_TOTAL + s;
    size_t vb1 = vb0 + (size_t)40 * S_TOTAL;
    split2(v1, hh, ll); g_Vth[vb0] = hh; g_Vtl[vb0] = ll;
    split2(v2, hh, ll); g_Vth[vb1] = hh; g_Vtl[vb1] = ll;
}

// ---------------- tensor-core flash attention ----------------
// block: 128 q-rows x one (head, segment); 8 warps = 16 q-rows each.
__global__ __launch_bounds__(256, 1) void attn_mma()
{
    extern __shared__ __nv_bfloat16 sm[];
    __nv_bfloat16* Qh = sm;                         // 128*88
    __nv_bfloat16* Ql = Qh + AQ * QSTR;
    __nv_bfloat16* Kh = Ql + AQ * QSTR;             // 2 x 64*88
    __nv_bfloat16* Kl = Kh + 2 * AK * QSTR;
    __nv_bfloat16* Vh = Kl + 2 * AK * QSTR;         // 2 x 80*72
    __nv_bfloat16* Vl = Vh + 2 * HEAD_DIM * VSTR;

    int tid = threadIdx.x, w = tid >> 5, lane = tid & 31;
    int qt = blockIdx.x, h = blockIdx.y, seg = blockIdx.z;

    size_t qoff = ((size_t)h * S_TOTAL + seg * SEG_LEN + qt * AQ) * HEAD_DIM;
    size_t koff = ((size_t)h * S_TOTAL + seg * SEG_LEN) * HEAD_DIM;
    size_t voff = (size_t)h * HEAD_DIM * S_TOTAL + seg * SEG_LEN;

    uint32_t uQh = s2u(Qh), uQl = s2u(Ql);
    uint32_t uKh = s2u(Kh), uKl = s2u(Kl);
    uint32_t uVh = s2u(Vh), uVl = s2u(Vl);

    // ---- prologue: load Q (2560 x 16B) + KV tile 0 ----
    #pragma unroll
    for (int j = 0; j < 10; j++) {
        int id = tid + j * 256;                 // 0..2559
        int c = id % 1280;
        int row = c / 10, off = c % 10;
        const __nv_bfloat16* src = (id < 1280 ? g_Qh : g_Ql) + qoff + row * HEAD_DIM + off * 8;
        uint32_t dst = (id < 1280 ? uQh : uQl) + (row * QSTR + off * 8) * 2;
        cpa16(dst, src);
    }
    #define LOADKV(tt, buf) do { \
        int _t = (tt); \
        _Pragma("unroll") \
        for (int _j = 0; _j < 10; _j++) { \
            int _id = tid + _j * 256; \
            int _arr = _id / 640, _c = _id % 640; \
            if (_arr < 2) { \
                int _row = _c / 10, _off = _c % 10; \
                const __nv_bfloat16* _s = (_arr == 0 ? g_Kh : g_Kl) + koff + (size_t)(_t * AK + _row) * HEAD_DIM + _off * 8; \
                uint32_t _d = (_arr == 0 ? uKh : uKl) + ((buf) * AK * QSTR + _row * QSTR + _off * 8) * 2; \
                cpa16(_d, _s); \
            } else { \
                int _row = _c / 8, _off = _c % 8; \
                const __nv_bfloat16* _s = (_arr == 2 ? g_Vth : g_Vtl) + voff + (size_t)_row * S_TOTAL + _t * AK + _off * 8; \
                uint32_t _d = (_arr == 2 ? uVh : uVl) + ((buf) * HEAD_DIM * VSTR + _row * VSTR + _off * 8) * 2; \
                cpa16(_d, _s); \
            } \
        } \
    } while (0)
    LOADKV(0, 0);
    CP_COMMIT();

    // ---- per-lane state ----
    float m0 = -INFINITY, m1 = -INFINITY, l0 = 0.f, l1 = 0.f;
    float oacc[10][4];
    #pragma unroll
    for (int nt = 0; nt < 10; nt++)
        #pragma unroll
        for (int v = 0; v < 4; v++) oacc[nt][v] = 0.f;

    // Q fragments (held in registers for all 16 tiles)
    uint32_t qfh[5][4], qfl[5][4];
    bool qloaded = false;

    const int NT_TILES = SEG_LEN / AK;   // 16
    for (int t = 0; t < NT_TILES; t++) {
        int buf = t & 1;
        if (t + 1 < NT_TILES) { LOADKV(t + 1, (t + 1) & 1); CP_COMMIT(); CP_WAIT(1); }
        else                  { CP_WAIT(0); }
        __syncthreads();

        if (!qloaded) {
            qloaded = true;
            int row = w * 16 + (lane & 15);
            #pragma unroll
            for (int ks = 0; ks < 5; ks++) {
                int ko = ks * 16 + (lane >> 4) * 8;
                ldmx4(uQh + (row * QSTR + ko) * 2, qfh[ks]);
                ldmx4(uQl + (row * QSTR + ko) * 2, qfl[ks]);
            }
        }

        // ---- S = Q K^T (split 3-product) ----
        float sacc[8][4];
        #pragma unroll
        for (int nt = 0; nt < 8; nt++)
            #pragma unroll
            for (int v = 0; v < 4; v++) sacc[nt][v] = 0.f;

        uint32_t kbase = (buf * AK * QSTR) * 2;
        #pragma unroll
        for (int ks = 0; ks < 5; ks++) {
            int k0 = ks * 16;
            #pragma unroll
            for (int nt = 0; nt < 8; nt++) {
                int row = nt * 8 + (lane & 7);
                int ko = k0 + ((lane >> 3) & 1) * 8;
                uint32_t bh[2], bl[2];
                ldmx2(uKh + kbase + (row * QSTR + ko) * 2, bh);
                ldmx2(uKl + kbase + (row * QSTR + ko) * 2, bl);
                mma16816(sacc[nt], qfh[ks], bh);
                mma16816(sacc[nt], qfh[ks], bl);
                mma16816(sacc[nt], qfl[ks], bh);
            }
        }

        // ---- online softmax (rows g=lane>>2 and g+8; quad lanes share a row) ----
        float tm0 = -INFINITY, tm1 = -INFINITY;
        #pragma unroll
        for (int nt = 0; nt < 8; nt++) {
            tm0 = fmaxf(tm0, fmaxf(sacc[nt][0], sacc[nt][1]));
            tm1 = fmaxf(tm1, fmaxf(sacc[nt][2], sacc[nt][3]));
        }
        #pragma unroll
        for (int off = 1; off <= 2; off <<= 1) {
            tm0 = fmaxf(tm0, __shfl_xor_sync(0xffffffffu, tm0, off));
            tm1 = fmaxf(tm1, __shfl_xor_sync(0xffffffffu, tm1, off));
        }
        float nm0 = fmaxf(m0, tm0), nm1 = fmaxf(m1, tm1);
        float al0 = fexp(m0 - nm0), al1 = fexp(m1 - nm1);
        m0 = nm0; m1 = nm1;
        #pragma unroll
        for (int nt = 0; nt < 10; nt++) {
            oacc[nt][0] *= al0; oacc[nt][1] *= al0;
            oacc[nt][2] *= al1; oacc[nt][3] *= al1;
        }

        uint32_t phA[8], phB[8], plA[8], plB[8];
        float sum0 = 0.f, sum1 = 0.f;
        #pragma unroll
        for (int nt = 0; nt < 8; nt++) {
            float p0 = fexp(sacc[nt][0] - m0);
            float p1 = fexp(sacc[nt][1] - m0);
            float p2 = fexp(sacc[nt][2] - m1);
            float p3 = fexp(sacc[nt][3] - m1);
            sum0 += p0 + p1; sum1 += p2 + p3;
            __nv_bfloat16 h0, l0b, h1, l1b;
            split2(p0, h0, l0b); split2(p1, h1, l1b);
            phA[nt] = packbf(h0, h1); plA[nt] = packbf(l0b, l1b);
            split2(p2, h0, l0b); split2(p3, h1, l1b);
            phB[nt] = packbf(h0, h1); plB[nt] = packbf(l0b, l1b);
        }
        #pragma unroll
        for (int off = 1; off <= 2; off <<= 1) {
            sum0 += __shfl_xor_sync(0xffffffffu, sum0, off);
            sum1 += __shfl_xor_sync(0xffffffffu, sum1, off);
        }
        l0 = l0 * al0 + sum0;
        l1 = l1 * al1 + sum1;

        // ---- O += P V (split 3-product); B from V^T tiles ----
        uint32_t vbase = (buf * HEAD_DIM * VSTR) * 2;
        #pragma unroll
        for (int j = 0; j < 4; j++) {
            uint32_t ah[4] = { phA[2*j], phB[2*j], phA[2*j+1], phB[2*j+1] };
            uint32_t alr[4] = { plA[2*j], plB[2*j], plA[2*j+1], plB[2*j+1] };
            int k0 = j * 16;
            #pragma unroll
            for (int nt = 0; nt < 10; nt++) {
                int row = nt * 8 + (lane & 7);
                int ko = k0 + ((lane >> 3) & 1) * 8;
                uint32_t vh[2], vl[2];
                ldmx2(uVh + vbase + (row * VSTR + ko) * 2, vh);
                ldmx2(uVl + vbase + (row * VSTR + ko) * 2, vl);
                mma16816(oacc[nt], ah, vh);
                mma16816(oacc[nt], ah, vl);
                mma16816(oacc[nt], alr, vh);
            }
        }
        __syncthreads();
    }
    #undef LOADKV

    // ---- epilogue: normalize + write split ctx into proj A-buffer ----
    float inv0 = 1.0f / l0, inv1 = 1.0f / l1;
    int g = lane >> 2, tq = lane & 3;
    int r0 = seg * SEG_LEN + qt * AQ + w * 16 + g;
    int r1 = r0 + 8;
    #pragma unroll
    for (int nt = 0; nt < 10; nt++) {
        int col = h * HEAD_DIM + nt * 8 + tq * 2;
        __nv_bfloat16 h0, lo0, h1, lo1;
        split2(oacc[nt][0] * inv0, h0, lo0);
        split2(oacc[nt][1] * inv0, h1, lo1);
        *(uint32_t*)&g_A2[(size_t)r0 * KP2 + col]         = packbf(h0, h1);
        *(uint32_t*)&g_A2[(size_t)r0 * KP2 + EMBED + col] = packbf(lo0, lo1);
        split2(oacc[nt][2] * inv1, h0, lo0);
        split2(oacc[nt][3] * inv1, h1, lo1);
        *(uint32_t*)&g_A2[(size_t)r1 * KP2 + col]         = packbf(h0, h1);
        *(uint32_t*)&g_A2[(size_t)r1 * KP2 + EMBED + col] = packbf(lo0, lo1);
    }
}

// ---------------- launch ----------------
extern "C" void kernel_launch(void* const* d_in, const int* in_sizes, int n_in,
                              void* d_out, int out_size)
{
    const float* x      = (const float*)d_in[0];
    const float* qkv_w  = (const float*)d_in[1];
    const float* qkv_b  = (const float*)d_in[2];
    const float* proj_w = (const float*)d_in[3];
    const float* proj_b = (const float*)d_in[4];
    const float* rope   = (const float*)d_in[5];
    float* out = (float*)d_out;

    float* qkv_p;
    __nv_bfloat16 *a2_p, *bqkv_p, *bproj_p;
    cudaGetSymbolAddress((void**)&qkv_p,   g_qkv);
    cudaGetSymbolAddress((void**)&a2_p,    g_A2);
    cudaGetSymbolAddress((void**)&bqkv_p,  g_Bqkv);
    cudaGetSymbolAddress((void**)&bproj_p, g_Bproj);

    const int gemm_smem = 3 * 20480;
    cudaFuncSetAttribute(hmma_gemm, cudaFuncAttributeMaxDynamicSharedMemorySize, gemm_smem);
    const int attn_smem = (2 * AQ * QSTR + 2 * 2 * AK * QSTR + 2 * 2 * HEAD_DIM * VSTR) * 2;
    cudaFuncSetAttribute(attn_mma, cudaFuncAttributeMaxDynamicSharedMemorySize, attn_smem);

    int nx = S_TOTAL * EMBED;
    int nw = 3 * EMBED * EMBED;
    int np = EMBED * EMBED;
    split_bf16<<<(nx + 255) / 256, 256>>>(x, a2_p, nx);
    split_bf16<<<(nw + 255) / 256, 256>>>(qkv_w, bqkv_p, nw);
    split_bf16<<<(np + 255) / 256, 256>>>(proj_w, bproj_p, np);

    // 1) QKV GEMM: [4096, 3840]
    hmma_gemm<<<dim3(3 * EMBED / BN, S_TOTAL / BM), 256, gemm_smem>>>(
        a2_p, bqkv_p, qkv_b, qkv_p, 3 * EMBED);

    // 2) rotary + split + transpose
    int nrot = S_TOTAL * HEADS * (HEAD_DIM / 2);
    rotary_split<<<(nrot + 255) / 256, 256>>>(rope);

    // 3) tensor-core attention -> writes split ctx into g_A2
    attn_mma<<<dim3(SEG_LEN / AQ, HEADS, NSEG), 256, attn_smem>>>();

    // 4) proj GEMM: [4096, 1280]
    hmma_gemm<<<dim3(EMBED / BN, S_TOTAL / BM), 256, gemm_smem>>>(
        a2_p, bproj_p, proj_b, out, EMBED);
}

// round 6
// speedup vs baseline: 2.5962x; 1.1452x over previous
#include <cuda_runtime.h>
#include <cuda_bf16.h>
#include <math.h>
#include <stdint.h>

#define S_TOTAL 4096
#define EMBED   1280
#define HEADS   16
#define HEAD_DIM 80
#define NSEG    4
#define SEG_LEN 1024

#define KP2     2560          // [hi|lo] bf16 storage cols per row
#define NKCH    40            // real K = 1280 -> 40 chunks of 32
#define BM      128
#define BN      128
#define KPAD    40            // gemm smem row stride (bf16)
#define TILEB   (128 * KPAD)  // one tile in bf16 elems (128 rows x 40)

// attention tiles
#define AQ      128
#define AK      64
#define QSTR    88            // q/k smem row stride
#define VSTR    72            // v^T smem row stride

// ---------------- scratch ----------------
__device__ float g_qkv [S_TOTAL * 3 * EMBED];                 // [S][3E] fp32
__device__ __nv_bfloat16 g_A2   [S_TOTAL * KP2];              // split activations [hi|lo]
__device__ __nv_bfloat16 g_Bqkv [3 * EMBED * KP2];
__device__ __nv_bfloat16 g_Bproj[EMBED * KP2];
__device__ __nv_bfloat16 g_Qh[HEADS * S_TOTAL * HEAD_DIM];    // [H][S][D] (scaled)
__device__ __nv_bfloat16 g_Ql[HEADS * S_TOTAL * HEAD_DIM];
__device__ __nv_bfloat16 g_Kh[HEADS * S_TOTAL * HEAD_DIM];
__device__ __nv_bfloat16 g_Kl[HEADS * S_TOTAL * HEAD_DIM];
__device__ __nv_bfloat16 g_Vth[HEADS * HEAD_DIM * S_TOTAL];   // [H][D][S]
__device__ __nv_bfloat16 g_Vtl[HEADS * HEAD_DIM * S_TOTAL];

// ---------------- helpers ----------------
__device__ __forceinline__ uint32_t s2u(const void* p) {
    uint32_t a;
    asm("{ .reg .u64 t; cvta.to.shared.u64 t, %1; cvt.u32.u64 %0, t; }" : "=r"(a) : "l"(p));
    return a;
}
__device__ __forceinline__ void cpa16(uint32_t dst, const void* src) {
    asm volatile("cp.async.cg.shared.global [%0], [%1], 16;" :: "r"(dst), "l"(src) : "memory");
}
#define CP_COMMIT() asm volatile("cp.async.commit_group;" ::: "memory")
#define CP_WAIT(n)  asm volatile("cp.async.wait_group %0;" :: "n"(n) : "memory")

__device__ __forceinline__ void ldmx4(uint32_t addr, uint32_t* r) {
    asm volatile("ldmatrix.sync.aligned.m8n8.x4.shared.b16 {%0,%1,%2,%3}, [%4];"
        : "=r"(r[0]), "=r"(r[1]), "=r"(r[2]), "=r"(r[3]) : "r"(addr));
}
__device__ __forceinline__ void ldmx2(uint32_t addr, uint32_t* r) {
    asm volatile("ldmatrix.sync.aligned.m8n8.x2.shared.b16 {%0,%1}, [%2];"
        : "=r"(r[0]), "=r"(r[1]) : "r"(addr));
}
__device__ __forceinline__ void mma16816(float* c, const uint32_t* a, const uint32_t* b) {
    asm volatile(
        "mma.sync.aligned.m16n8k16.row.col.f32.bf16.bf16.f32 "
        "{%0,%1,%2,%3},{%4,%5,%6,%7},{%8,%9},{%0,%1,%2,%3};"
        : "+f"(c[0]), "+f"(c[1]), "+f"(c[2]), "+f"(c[3])
        : "r"(a[0]), "r"(a[1]), "r"(a[2]), "r"(a[3]), "r"(b[0]), "r"(b[1]));
}
// e^x on the FMA pipe (exp2 poly)
__device__ __forceinline__ float fexp(float x) {
    float t = x * 1.4426950408889634f;
    t = fmaxf(t, -126.0f);
    float fi = floorf(t);
    float f = t - fi;
    float p = 1.33336498e-3f;
    p = fmaf(p, f, 9.61011733e-3f);
    p = fmaf(p, f, 5.55036243e-2f);
    p = fmaf(p, f, 2.40226506e-1f);
    p = fmaf(p, f, 6.93147182e-1f);
    p = fmaf(p, f, 1.0f);
    return p * __int_as_float(((int)fi + 127) << 23);
}
__device__ __forceinline__ void split2(float v, __nv_bfloat16& h, __nv_bfloat16& l) {
    h = __float2bfloat16(v);
    l = __float2bfloat16(v - __bfloat162float(h));
}
__device__ __forceinline__ uint32_t packbf(__nv_bfloat16 a, __nv_bfloat16 b) {
    return (uint32_t)__bfloat16_as_ushort(a) | ((uint32_t)__bfloat16_as_ushort(b) << 16);
}

// ---------------- fp32 -> bf16 [hi|lo] split ----------------
__global__ void split_bf16(const float* __restrict__ src, __nv_bfloat16* __restrict__ dst, int total)
{
    int i = blockIdx.x * 256 + threadIdx.x;
    if (i >= total) return;
    int r = i / EMBED, c = i % EMBED;
    float a = src[i];
    __nv_bfloat16 h = __float2bfloat16(a);
    float res = a - __bfloat162float(h);
    dst[(size_t)r * KP2 + c]         = h;
    dst[(size_t)r * KP2 + EMBED + c] = __float2bfloat16(res);
}

// ---------------- HMMA split-bf16 GEMM (shared-fragment 3-product) --------------
// Per real k-chunk (32): load Ah/Al/Bh/Bl tiles once, issue ah*bh + ah*bl + al*bh
// from the same register fragments. MMA:ldmatrix = 3:1.
__global__ __launch_bounds__(256, 2) void hmma_gemm(
    const __nv_bfloat16* __restrict__ A,
    const __nv_bfloat16* __restrict__ B,
    const float* __restrict__ bias,
    float* __restrict__ C, int Ntot)
{
    extern __shared__ char smraw[];
    // stage s, tile t in {Ah, Al, Bh, Bl}: base + (s*4 + t) * TILEB * 2 bytes
    uint32_t smb = s2u(smraw);

    int tid = threadIdx.x, wid = tid >> 5, lane = tid & 31;
    int bm = blockIdx.y * BM, bn = blockIdx.x * BN;
    int wm = (wid >> 2) * 64;
    int wn = (wid & 3) * 32;

    float acc[4][4][4];
    #pragma unroll
    for (int i = 0; i < 4; i++)
        #pragma unroll
        for (int j = 0; j < 4; j++)
            #pragma unroll
            for (int v = 0; v < 4; v++) acc[i][j][v] = 0.f;

    // loader: 4 tiles x 128 rows x 64B = 2048 x 16B ops; 8 per thread
    #define LOADC(cc, buf) do { \
        int _k = (cc) * 32; \
        _Pragma("unroll") \
        for (int _t = 0; _t < 8; _t++) { \
            int _id = tid + _t * 256;          /* 0..2047 */ \
            int _tile = _id >> 9;              /* 0 Ah, 1 Al, 2 Bh, 3 Bl */ \
            int _c = _id & 511; \
            int _r = _c >> 2, _o = (_c & 3) * 8; \
            const __nv_bfloat16* _base = (_tile < 2) ? (A + (size_t)bm * KP2) \
                                                     : (B + (size_t)bn * KP2); \
            int _kk = _k + ((_tile & 1) ? EMBED : 0); \
            uint32_t _dst = smb + (((buf) * 4 + _tile) * TILEB + _r * KPAD + _o) * 2; \
            cpa16(_dst, _base + (size_t)_r * KP2 + _kk + _o); \
        } \
    } while (0)

    LOADC(0, 0);
    CP_COMMIT();

    for (int i = 0; i < NKCH; i++) {
        int buf = i & 1;
        if (i + 1 < NKCH) { LOADC(i + 1, (i + 1) & 1); CP_COMMIT(); CP_WAIT(1); }
        else              { CP_WAIT(0); }
        __syncthreads();

        uint32_t uAh = smb + ((buf * 4 + 0) * TILEB) * 2;
        uint32_t uAl = smb + ((buf * 4 + 1) * TILEB) * 2;
        uint32_t uBh = smb + ((buf * 4 + 2) * TILEB) * 2;
        uint32_t uBl = smb + ((buf * 4 + 3) * TILEB) * 2;

        #pragma unroll
        for (int ks = 0; ks < 2; ks++) {
            int k0 = ks * 16;
            uint32_t bh[4][2], bl[4][2];
            #pragma unroll
            for (int nt = 0; nt < 4; nt++) {
                int row = wn + nt * 8 + (lane & 7);
                int ko = k0 + ((lane >> 3) & 1) * 8;
                ldmx2(uBh + (row * KPAD + ko) * 2, bh[nt]);
                ldmx2(uBl + (row * KPAD + ko) * 2, bl[nt]);
            }
            #pragma unroll
            for (int mt = 0; mt < 4; mt++) {
                int row = wm + mt * 16 + (lane & 15);
                int ko = k0 + (lane >> 4) * 8;
                uint32_t ah[4], al[4];
                ldmx4(uAh + (row * KPAD + ko) * 2, ah);
                ldmx4(uAl + (row * KPAD + ko) * 2, al);
                #pragma unroll
                for (int nt = 0; nt < 4; nt++) {
                    mma16816(acc[mt][nt], ah, bh[nt]);
                    mma16816(acc[mt][nt], ah, bl[nt]);
                    mma16816(acc[mt][nt], al, bh[nt]);
                }
            }
        }
        __syncthreads();
    }
    #undef LOADC

    int g = lane >> 2, t = lane & 3;
    #pragma unroll
    for (int mt = 0; mt < 4; mt++) {
        #pragma unroll
        for (int nt = 0; nt < 4; nt++) {
            int row = bm + wm + mt * 16 + g;
            int col = bn + wn + nt * 8 + t * 2;
            float b0 = bias[col], b1 = bias[col + 1];
            float2* p0 = (float2*)(C + (size_t)row * Ntot + col);
            float2* p1 = (float2*)(C + (size_t)(row + 8) * Ntot + col);
            *p0 = make_float2(acc[mt][nt][0] + b0, acc[mt][nt][1] + b1);
            *p1 = make_float2(acc[mt][nt][2] + b0, acc[mt][nt][3] + b1);
        }
    }
}

// ---------------- rotary + split + transpose scatter ----------------
__global__ void rotary_split(const float* __restrict__ rope)
{
    int idx = blockIdx.x * blockDim.x + threadIdx.x;
    const int TOT = S_TOTAL * HEADS * (HEAD_DIM / 2);
    if (idx >= TOT) return;
    int d2 = idx % (HEAD_DIM / 2);
    int h  = (idx / (HEAD_DIM / 2)) % HEADS;
    int s  = idx / ((HEAD_DIM / 2) * HEADS);

    float fr = rope[s * (HEAD_DIM / 2) + d2];
    float c = cosf(fr), sn = sinf(fr);
    const float scale = 0.111803398875f;  // 1/sqrt(80)

    const float* qk = g_qkv + (size_t)s * 3 * EMBED;
    int hb = h * HEAD_DIM;
    float q1 = qk[hb + d2],              q2 = qk[hb + d2 + 40];
    float k1 = qk[EMBED + hb + d2],      k2 = qk[EMBED + hb + d2 + 40];
    float v1 = qk[2 * EMBED + hb + d2],  v2 = qk[2 * EMBED + hb + d2 + 40];

    float qa = (q1 * c - q2 * sn) * scale;
    float qb = (q2 * c + q1 * sn) * scale;
    float ka = k1 * c - k2 * sn;
    float kb = k2 * c + k1 * sn;

    size_t base = (size_t)h * S_TOTAL * HEAD_DIM + (size_t)s * HEAD_DIM;
    __nv_bfloat16 hh, ll;
    split2(qa, hh, ll); g_Qh[base + d2] = hh;      g_Ql[base + d2] = ll;
    split2(qb, hh, ll); g_Qh[base + d2 + 40] = hh; g_Ql[base + d2 + 40] = ll;
    split2(ka, hh, ll); g_Kh[base + d2] = hh;      g_Kl[base + d2] = ll;
    split2(kb, hh, ll); g_Kh[base + d2 + 40] = hh; g_Kl[base + d2 + 40] = ll;

    size_t vb0 = (size_t)h * HEAD_DIM * S_TOTAL + (size_t)d2 * S_TOTAL + s;
    size_t vb1 = vb0 + (size_t)40 * S_TOTAL;
    split2(v1, hh, ll); g_Vth[vb0] = hh; g_Vtl[vb0] = ll;
    split2(v2, hh, ll); g_Vth[vb1] = hh; g_Vtl[vb1] = ll;
}

// ---------------- tensor-core flash attention ----------------
__global__ __launch_bounds__(256, 1) void attn_mma()
{
    extern __shared__ __nv_bfloat16 sm[];
    __nv_bfloat16* Qh = sm;                         // 128*88
    __nv_bfloat16* Ql = Qh + AQ * QSTR;
    __nv_bfloat16* Kh = Ql + AQ * QSTR;             // 2 x 64*88
    __nv_bfloat16* Kl = Kh + 2 * AK * QSTR;
    __nv_bfloat16* Vh = Kl + 2 * AK * QSTR;         // 2 x 80*72
    __nv_bfloat16* Vl = Vh + 2 * HEAD_DIM * VSTR;

    int tid = threadIdx.x, w = tid >> 5, lane = tid & 31;
    int qt = blockIdx.x, h = blockIdx.y, seg = blockIdx.z;

    size_t qoff = ((size_t)h * S_TOTAL + seg * SEG_LEN + qt * AQ) * HEAD_DIM;
    size_t koff = ((size_t)h * S_TOTAL + seg * SEG_LEN) * HEAD_DIM;
    size_t voff = (size_t)h * HEAD_DIM * S_TOTAL + seg * SEG_LEN;

    uint32_t uQh = s2u(Qh), uQl = s2u(Ql);
    uint32_t uKh = s2u(Kh), uKl = s2u(Kl);
    uint32_t uVh = s2u(Vh), uVl = s2u(Vl);

    #pragma unroll
    for (int j = 0; j < 10; j++) {
        int id = tid + j * 256;
        int c = id % 1280;
        int row = c / 10, off = c % 10;
        const __nv_bfloat16* src = (id < 1280 ? g_Qh : g_Ql) + qoff + row * HEAD_DIM + off * 8;
        uint32_t dst = (id < 1280 ? uQh : uQl) + (row * QSTR + off * 8) * 2;
        cpa16(dst, src);
    }
    #define LOADKV(tt, buf) do { \
        int _t = (tt); \
        _Pragma("unroll") \
        for (int _j = 0; _j < 10; _j++) { \
            int _id = tid + _j * 256; \
            int _arr = _id / 640, _c = _id % 640; \
            if (_arr < 2) { \
                int _row = _c / 10, _off = _c % 10; \
                const __nv_bfloat16* _s = (_arr == 0 ? g_Kh : g_Kl) + koff + (size_t)(_t * AK + _row) * HEAD_DIM + _off * 8; \
                uint32_t _d = (_arr == 0 ? uKh : uKl) + ((buf) * AK * QSTR + _row * QSTR + _off * 8) * 2; \
                cpa16(_d, _s); \
            } else { \
                int _row = _c / 8, _off = _c % 8; \
                const __nv_bfloat16* _s = (_arr == 2 ? g_Vth : g_Vtl) + voff + (size_t)_row * S_TOTAL + _t * AK + _off * 8; \
                uint32_t _d = (_arr == 2 ? uVh : uVl) + ((buf) * HEAD_DIM * VSTR + _row * VSTR + _off * 8) * 2; \
                cpa16(_d, _s); \
            } \
        } \
    } while (0)
    LOADKV(0, 0);
    CP_COMMIT();

    float m0 = -INFINITY, m1 = -INFINITY, l0 = 0.f, l1 = 0.f;
    float oacc[10][4];
    #pragma unroll
    for (int nt = 0; nt < 10; nt++)
        #pragma unroll
        for (int v = 0; v < 4; v++) oacc[nt][v] = 0.f;

    uint32_t qfh[5][4], qfl[5][4];
    bool qloaded = false;

    const int NT_TILES = SEG_LEN / AK;
    for (int t = 0; t < NT_TILES; t++) {
        int buf = t & 1;
        if (t + 1 < NT_TILES) { LOADKV(t + 1, (t + 1) & 1); CP_COMMIT(); CP_WAIT(1); }
        else                  { CP_WAIT(0); }
        __syncthreads();

        if (!qloaded) {
            qloaded = true;
            int row = w * 16 + (lane & 15);
            #pragma unroll
            for (int ks = 0; ks < 5; ks++) {
                int ko = ks * 16 + (lane >> 4) * 8;
                ldmx4(uQh + (row * QSTR + ko) * 2, qfh[ks]);
                ldmx4(uQl + (row * QSTR + ko) * 2, qfl[ks]);
            }
        }

        float sacc[8][4];
        #pragma unroll
        for (int nt = 0; nt < 8; nt++)
            #pragma unroll
            for (int v = 0; v < 4; v++) sacc[nt][v] = 0.f;

        uint32_t kbase = (buf * AK * QSTR) * 2;
        #pragma unroll
        for (int ks = 0; ks < 5; ks++) {
            int k0 = ks * 16;
            #pragma unroll
            for (int nt = 0; nt < 8; nt++) {
                int row = nt * 8 + (lane & 7);
                int ko = k0 + ((lane >> 3) & 1) * 8;
                uint32_t bh[2], bl[2];
                ldmx2(uKh + kbase + (row * QSTR + ko) * 2, bh);
                ldmx2(uKl + kbase + (row * QSTR + ko) * 2, bl);
                mma16816(sacc[nt], qfh[ks], bh);
                mma16816(sacc[nt], qfh[ks], bl);
                mma16816(sacc[nt], qfl[ks], bh);
            }
        }

        float tm0 = -INFINITY, tm1 = -INFINITY;
        #pragma unroll
        for (int nt = 0; nt < 8; nt++) {
            tm0 = fmaxf(tm0, fmaxf(sacc[nt][0], sacc[nt][1]));
            tm1 = fmaxf(tm1, fmaxf(sacc[nt][2], sacc[nt][3]));
        }
        #pragma unroll
        for (int off = 1; off <= 2; off <<= 1) {
            tm0 = fmaxf(tm0, __shfl_xor_sync(0xffffffffu, tm0, off));
            tm1 = fmaxf(tm1, __shfl_xor_sync(0xffffffffu, tm1, off));
        }
        float nm0 = fmaxf(m0, tm0), nm1 = fmaxf(m1, tm1);
        float al0 = fexp(m0 - nm0), al1 = fexp(m1 - nm1);
        m0 = nm0; m1 = nm1;
        #pragma unroll
        for (int nt = 0; nt < 10; nt++) {
            oacc[nt][0] *= al0; oacc[nt][1] *= al0;
            oacc[nt][2] *= al1; oacc[nt][3] *= al1;
        }

        uint32_t phA[8], phB[8], plA[8], plB[8];
        float sum0 = 0.f, sum1 = 0.f;
        #pragma unroll
        for (int nt = 0; nt < 8; nt++) {
            float p0 = fexp(sacc[nt][0] - m0);
            float p1 = fexp(sacc[nt][1] - m0);
            float p2 = fexp(sacc[nt][2] - m1);
            float p3 = fexp(sacc[nt][3] - m1);
            sum0 += p0 + p1; sum1 += p2 + p3;
            __nv_bfloat16 h0, l0b, h1, l1b;
            split2(p0, h0, l0b); split2(p1, h1, l1b);
            phA[nt] = packbf(h0, h1); plA[nt] = packbf(l0b, l1b);
            split2(p2, h0, l0b); split2(p3, h1, l1b);
            phB[nt] = packbf(h0, h1); plB[nt] = packbf(l0b, l1b);
        }
        #pragma unroll
        for (int off = 1; off <= 2; off <<= 1) {
            sum0 += __shfl_xor_sync(0xffffffffu, sum0, off);
            sum1 += __shfl_xor_sync(0xffffffffu, sum1, off);
        }
        l0 = l0 * al0 + sum0;
        l1 = l1 * al1 + sum1;

        uint32_t vbase = (buf * HEAD_DIM * VSTR) * 2;
        #pragma unroll
        for (int j = 0; j < 4; j++) {
            uint32_t ah[4] = { phA[2*j], phB[2*j], phA[2*j+1], phB[2*j+1] };
            uint32_t alr[4] = { plA[2*j], plB[2*j], plA[2*j+1], plB[2*j+1] };
            int k0 = j * 16;
            #pragma unroll
            for (int nt = 0; nt < 10; nt++) {
                int row = nt * 8 + (lane & 7);
                int ko = k0 + ((lane >> 3) & 1) * 8;
                uint32_t vh[2], vl[2];
                ldmx2(uVh + vbase + (row * VSTR + ko) * 2, vh);
                ldmx2(uVl + vbase + (row * VSTR + ko) * 2, vl);
                mma16816(oacc[nt], ah, vh);
                mma16816(oacc[nt], ah, vl);
                mma16816(oacc[nt], alr, vh);
            }
        }
        __syncthreads();
    }
    #undef LOADKV

    float inv0 = 1.0f / l0, inv1 = 1.0f / l1;
    int g = lane >> 2, tq = lane & 3;
    int r0 = seg * SEG_LEN + qt * AQ + w * 16 + g;
    int r1 = r0 + 8;
    #pragma unroll
    for (int nt = 0; nt < 10; nt++) {
        int col = h * HEAD_DIM + nt * 8 + tq * 2;
        __nv_bfloat16 h0, lo0, h1, lo1;
        split2(oacc[nt][0] * inv0, h0, lo0);
        split2(oacc[nt][1] * inv0, h1, lo1);
        *(uint32_t*)&g_A2[(size_t)r0 * KP2 + col]         = packbf(h0, h1);
        *(uint32_t*)&g_A2[(size_t)r0 * KP2 + EMBED + col] = packbf(lo0, lo1);
        split2(oacc[nt][2] * inv1, h0, lo0);
        split2(oacc[nt][3] * inv1, h1, lo1);
        *(uint32_t*)&g_A2[(size_t)r1 * KP2 + col]         = packbf(h0, h1);
        *(uint32_t*)&g_A2[(size_t)r1 * KP2 + EMBED + col] = packbf(lo0, lo1);
    }
}

// ---------------- launch ----------------
extern "C" void kernel_launch(void* const* d_in, const int* in_sizes, int n_in,
                              void* d_out, int out_size)
{
    const float* x      = (const float*)d_in[0];
    const float* qkv_w  = (const float*)d_in[1];
    const float* qkv_b  = (const float*)d_in[2];
    const float* proj_w = (const float*)d_in[3];
    const float* proj_b = (const float*)d_in[4];
    const float* rope   = (const float*)d_in[5];
    float* out = (float*)d_out;

    float* qkv_p;
    __nv_bfloat16 *a2_p, *bqkv_p, *bproj_p;
    cudaGetSymbolAddress((void**)&qkv_p,   g_qkv);
    cudaGetSymbolAddress((void**)&a2_p,    g_A2);
    cudaGetSymbolAddress((void**)&bqkv_p,  g_Bqkv);
    cudaGetSymbolAddress((void**)&bproj_p, g_Bproj);

    const int gemm_smem = 2 * 4 * TILEB * 2;   // 81920 B
    cudaFuncSetAttribute(hmma_gemm, cudaFuncAttributeMaxDynamicSharedMemorySize, gemm_smem);
    const int attn_smem = (2 * AQ * QSTR + 2 * 2 * AK * QSTR + 2 * 2 * HEAD_DIM * VSTR) * 2;
    cudaFuncSetAttribute(attn_mma, cudaFuncAttributeMaxDynamicSharedMemorySize, attn_smem);

    int nx = S_TOTAL * EMBED;
    int nw = 3 * EMBED * EMBED;
    int np = EMBED * EMBED;
    split_bf16<<<(nx + 255) / 256, 256>>>(x, a2_p, nx);
    split_bf16<<<(nw + 255) / 256, 256>>>(qkv_w, bqkv_p, nw);
    split_bf16<<<(np + 255) / 256, 256>>>(proj_w, bproj_p, np);

    // 1) QKV GEMM: [4096, 3840]
    hmma_gemm<<<dim3(3 * EMBED / BN, S_TOTAL / BM), 256, gemm_smem>>>(
        a2_p, bqkv_p, qkv_b, qkv_p, 3 * EMBED);

    // 2) rotary + split + transpose
    int nrot = S_TOTAL * HEADS * (HEAD_DIM / 2);
    rotary_split<<<(nrot + 255) / 256, 256>>>(rope);

    // 3) tensor-core attention -> writes split ctx into g_A2
    attn_mma<<<dim3(SEG_LEN / AQ, HEADS, NSEG), 256, attn_smem>>>();

    // 4) proj GEMM: [4096, 1280]
    hmma_gemm<<<dim3(EMBED / BN, S_TOTAL / BM), 256, gemm_smem>>>(
        a2_p, bproj_p, proj_b, out, EMBED);
}